// round 13
// baseline (speedup 1.0000x reference)
#include <cuda_runtime.h>
#include <math.h>

// LocalHolder2D: out = sum_i w_i * log10(maxpool_k(x)), k = 3,5,7
// x: (B=8, C=64, H=256, W=256) fp32, strictly positive.
// Centered OLS weights (sum w_i = 0) -> log10(1/(H*W)) offset cancels.
//
// R13 = R12 (one-warp blocks, register ring, VIMNMX3 int max tree, L2
// prefetch of row y+12) with launch_bounds (32,16) -> (32,18). R12's
// prefetch dropped register usage to 107, so an 18-block budget (113 regs)
// is NOT a squeeze — same schedule, but the residency cap rises from 16 to
// 18 one-warp blocks/SM (~+35% latency hiding on a 44%-stalled kernel).

#define HH 256
#define WW 256
#define RPB 32                 /* rows per warp-task */
#define THREADS 32
#define NEG_I ((int)0xff800000)   /* -inf bits */
#define PFD 12                 /* prefetch distance in rows */

static __device__ __forceinline__ int imax2(int a, int b) { return a > b ? a : b; }

static __device__ __forceinline__ void l2_prefetch(const int* p) {
    asm volatile("prefetch.global.L2 [%0];" :: "l"(p));
}

__global__ __launch_bounds__(THREADS, 18)
void holder_kernel(const int* __restrict__ x, float* __restrict__ out,
                   float w3, float w5, float w7)
{
    const int lane = threadIdx.x & 31;
    const int task = blockIdx.x;                    // 4096 tasks
    const int plane = task >> 3;
    const int y0 = (task & 7) * RPB;                // multiple of 8

    const int* __restrict__ src = x   + (size_t)plane * (HH * WW) + lane * 8;
    float*     __restrict__ dst = out + (size_t)plane * (HH * WW) + lane * 8;

    const unsigned FULL = 0xffffffffu;
    const bool l0 = (lane == 0), l31 = (lane == 31);

    // ring[slot][col]; slot for row r is r & 7 (y0 % 8 == 0).
    int ring[8][8];

    // Prologue prefetch: rows y0+4 .. y0+PFD-1.
    #pragma unroll
    for (int j = 4; j < PFD; ++j) {
        const int row = y0 + j;
        if (row < HH) l2_prefetch(src + row * WW);
    }

    // Prologue: rows y0-3 .. y0+3 -> slots (j+5)&7 for j=0..6.
    #pragma unroll
    for (int j = 0; j < 7; ++j) {
        const int row = y0 - 3 + j;
        const int s = (j + 5) & 7;
        if (row >= 0) {
            const int4* rp = (const int4*)(src + row * WW);
            int4 a = rp[0], b = rp[1];
            ring[s][0] = a.x; ring[s][1] = a.y; ring[s][2] = a.z; ring[s][3] = a.w;
            ring[s][4] = b.x; ring[s][5] = b.y; ring[s][6] = b.z; ring[s][7] = b.w;
        } else {
            #pragma unroll
            for (int t = 0; t < 8; ++t) ring[s][t] = NEG_I;
        }
    }

    for (int ib = 0; ib < RPB; ib += 8) {
        #pragma unroll
        for (int u = 0; u < 8; ++u) {
            const int y = y0 + ib + u;            // output row; y & 7 == u
            // L2 prefetch far ahead (one inst covers the whole 1KB row).
            {
                const int prow = y + PFD;
                if (prow < HH) l2_prefetch(src + prow * WW);
            }
            // Prefetch row y+4 into slot (u+4)&7 (vacated row y-4).
            {
                const int row = y + 4;
                const int s = (u + 4) & 7;
                if (row < HH) {
                    const int4* rp = (const int4*)(src + row * WW);
                    int4 a = rp[0], b = rp[1];
                    ring[s][0] = a.x; ring[s][1] = a.y; ring[s][2] = a.z; ring[s][3] = a.w;
                    ring[s][4] = b.x; ring[s][5] = b.y; ring[s][6] = b.z; ring[s][7] = b.w;
                } else {
                    #pragma unroll
                    for (int t = 0; t < 8; ++t) ring[s][t] = NEG_I;
                }
            }

            int v[8];
            float acc[8];

            // ---- k = 3 ----
            #pragma unroll
            for (int j = 0; j < 8; ++j)
                v[j] = __vimax3_s32(ring[(u + 7) & 7][j], ring[u][j],
                                    ring[(u + 1) & 7][j]);
            {
                int L = __shfl_up_sync  (FULL, v[7], 1); if (l0)  L = NEG_I;
                int R = __shfl_down_sync(FULL, v[0], 1); if (l31) R = NEG_I;
                int m0 = __vimax3_s32(L, v[0], v[1]);
                int m7 = __vimax3_s32(v[6], v[7], R);
                acc[0] = w3 * __log2f(__int_as_float(m0));
                #pragma unroll
                for (int j = 1; j < 7; ++j)
                    acc[j] = w3 * __log2f(__int_as_float(
                                 __vimax3_s32(v[j - 1], v[j], v[j + 1])));
                acc[7] = w3 * __log2f(__int_as_float(m7));
            }

            // ---- k = 5 ----
            #pragma unroll
            for (int j = 0; j < 8; ++j)
                v[j] = __vimax3_s32(v[j], ring[(u + 6) & 7][j],
                                    ring[(u + 2) & 7][j]);
            {
                int p01 = imax2(v[0], v[1]), p23 = imax2(v[2], v[3]);
                int p45 = imax2(v[4], v[5]), p67 = imax2(v[6], v[7]);
                int Lp = __shfl_up_sync  (FULL, p67, 1);
                int L7 = __shfl_up_sync  (FULL, v[7], 1);
                int R0 = __shfl_down_sync(FULL, v[0], 1);
                int Rp = __shfl_down_sync(FULL, p01, 1);
                if (l0)  { Lp = NEG_I; L7 = NEG_I; }
                if (l31) { R0 = NEG_I; Rp = NEG_I; }
                int m[8];
                m[0] = __vimax3_s32(Lp,  p01, v[2]);
                m[1] = __vimax3_s32(L7,  p01, p23);
                m[2] = __vimax3_s32(p01, p23, v[4]);
                m[3] = __vimax3_s32(v[1], p23, p45);
                m[4] = __vimax3_s32(p23, p45, v[6]);
                m[5] = __vimax3_s32(v[3], p45, p67);
                m[6] = __vimax3_s32(p45, p67, R0);
                m[7] = __vimax3_s32(v[5], p67, Rp);
                #pragma unroll
                for (int j = 0; j < 8; ++j)
                    acc[j] = fmaf(w5, __log2f(__int_as_float(m[j])), acc[j]);
            }

            // ---- k = 7 ----
            #pragma unroll
            for (int j = 0; j < 8; ++j)
                v[j] = __vimax3_s32(v[j], ring[(u + 5) & 7][j],
                                    ring[(u + 3) & 7][j]);
            {
                int p01 = imax2(v[0], v[1]), p23 = imax2(v[2], v[3]);
                int p45 = imax2(v[4], v[5]), p67 = imax2(v[6], v[7]);
                int a03 = imax2(p01, p23),   a47 = imax2(p45, p67);
                int suf3 = imax2(v[5], p67); // cols 5..7
                int pre3 = imax2(p01, v[2]); // cols 0..2
                int Ls  = __shfl_up_sync  (FULL, suf3, 1);
                int Lq  = __shfl_up_sync  (FULL, p67, 1);
                int L7v = __shfl_up_sync  (FULL, v[7], 1);
                int R0v = __shfl_down_sync(FULL, v[0], 1);
                int Rq  = __shfl_down_sync(FULL, p01, 1);
                int Rp3 = __shfl_down_sync(FULL, pre3, 1);
                if (l0)  { Ls = NEG_I; Lq = NEG_I; L7v = NEG_I; }
                if (l31) { R0v = NEG_I; Rq = NEG_I; Rp3 = NEG_I; }
                int m[8];
                m[0] = imax2(Ls, a03);               // -3..3
                m[1] = __vimax3_s32(Lq,  a03, v[4]); // -2..4
                m[2] = __vimax3_s32(L7v, a03, p45);  // -1..5
                m[3] = __vimax3_s32(a03, p45, v[6]); //  0..6
                m[4] = __vimax3_s32(v[1], p23, a47); //  1..7
                m[5] = __vimax3_s32(p23, a47, R0v);  //  2..8
                m[6] = __vimax3_s32(v[3], a47, Rq);  //  3..9
                m[7] = imax2(a47, Rp3);              //  4..10
                #pragma unroll
                for (int j = 0; j < 8; ++j)
                    acc[j] = fmaf(w7, __log2f(__int_as_float(m[j])), acc[j]);
            }

            float* dp = dst + y * WW;
            ((float4*)dp)[0] = make_float4(acc[0], acc[1], acc[2], acc[3]);
            ((float4*)dp)[1] = make_float4(acc[4], acc[5], acc[6], acc[7]);
        }
    }
}

extern "C" void kernel_launch(void* const* d_in, const int* in_sizes, int n_in,
                              void* d_out, int out_size)
{
    const int* x = (const int*)d_in[0];
    float* out = (float*)d_out;

    const int planes = in_sizes[0] / (HH * WW);     // 512

    // Closed-form OLS slope weights (double on host); fold in log10(2).
    double l3 = log10(3.0), l5 = log10(5.0), l7 = log10(7.0);
    double mean = (l3 + l5 + l7) / 3.0;
    double c3 = l3 - mean, c5 = l5 - mean, c7 = l7 - mean;
    double s = c3 * c3 + c5 * c5 + c7 * c7;
    double L10_2 = 0.30102999566398119521;
    float w3 = (float)((c3 / s) * L10_2);
    float w5 = (float)((c5 / s) * L10_2);
    float w7 = (float)((c7 / s) * L10_2);

    const int tasks = planes * (HH / RPB);          // 4096
    dim3 grid(tasks);                               // one warp per block
    dim3 block(THREADS);
    holder_kernel<<<grid, block>>>(x, out, w3, w5, w7);
}

// round 14
// speedup vs baseline: 1.0656x; 1.0656x over previous
#include <cuda_runtime.h>
#include <math.h>

// LocalHolder2D: out = sum_i w_i * log10(maxpool_k(x)), k = 3,5,7
// x: (B=8, C=64, H=256, W=256) fp32, strictly positive.
// Centered OLS weights (sum w_i = 0) -> log10(1/(H*W)) offset cancels.
//
// R14 = R12 (one-warp blocks, register ring, VIMNMX3 int max tree, L2
// prefetch of row y+12, launch_bounds (32,16) — the 107-reg schedule is
// load-bearing, R8/R13 both showed tighter budgets reschedule and lose)
// + second prefetch stage: prefetch.global.L1 of row y+6. Pipeline:
//   DRAM --(y+12 L2 pf, 8-iter slack)--> L2 --(y+6 L1 pf, 2-iter
//   slack)--> L1 --(demand LDG, 1-iter slack)--> regs (L1 hit ~39cyc).
// Two extra no-writeback LSU insts per 8-output iteration.

#define HH 256
#define WW 256
#define RPB 32                 /* rows per warp-task */
#define THREADS 32
#define NEG_I ((int)0xff800000)   /* -inf bits */
#define PFD2 12                /* L2 prefetch distance in rows */
#define PFD1 6                 /* L1 prefetch distance in rows */

static __device__ __forceinline__ int imax2(int a, int b) { return a > b ? a : b; }

static __device__ __forceinline__ void l2_prefetch(const int* p) {
    asm volatile("prefetch.global.L2 [%0];" :: "l"(p));
}
static __device__ __forceinline__ void l1_prefetch(const int* p) {
    asm volatile("prefetch.global.L1 [%0];" :: "l"(p));
}

__global__ __launch_bounds__(THREADS, 16)
void holder_kernel(const int* __restrict__ x, float* __restrict__ out,
                   float w3, float w5, float w7)
{
    const int lane = threadIdx.x & 31;
    const int task = blockIdx.x;                    // 4096 tasks
    const int plane = task >> 3;
    const int y0 = (task & 7) * RPB;                // multiple of 8

    const int* __restrict__ src = x   + (size_t)plane * (HH * WW) + lane * 8;
    float*     __restrict__ dst = out + (size_t)plane * (HH * WW) + lane * 8;

    const unsigned FULL = 0xffffffffu;
    const bool l0 = (lane == 0), l31 = (lane == 31);

    // ring[slot][col]; slot for row r is r & 7 (y0 % 8 == 0).
    int ring[8][8];

    // Prologue prefetch: L2 for rows y0+4 .. y0+PFD2-1, L1 for y0+4..y0+PFD1-1.
    #pragma unroll
    for (int j = 4; j < PFD2; ++j) {
        const int row = y0 + j;
        if (row < HH) l2_prefetch(src + row * WW);
    }
    #pragma unroll
    for (int j = 4; j < PFD1; ++j) {
        const int row = y0 + j;
        if (row < HH) l1_prefetch(src + row * WW);
    }

    // Prologue: rows y0-3 .. y0+3 -> slots (j+5)&7 for j=0..6.
    #pragma unroll
    for (int j = 0; j < 7; ++j) {
        const int row = y0 - 3 + j;
        const int s = (j + 5) & 7;
        if (row >= 0) {
            const int4* rp = (const int4*)(src + row * WW);
            int4 a = rp[0], b = rp[1];
            ring[s][0] = a.x; ring[s][1] = a.y; ring[s][2] = a.z; ring[s][3] = a.w;
            ring[s][4] = b.x; ring[s][5] = b.y; ring[s][6] = b.z; ring[s][7] = b.w;
        } else {
            #pragma unroll
            for (int t = 0; t < 8; ++t) ring[s][t] = NEG_I;
        }
    }

    for (int ib = 0; ib < RPB; ib += 8) {
        #pragma unroll
        for (int u = 0; u < 8; ++u) {
            const int y = y0 + ib + u;            // output row; y & 7 == u
            // Far L2 prefetch + near L1 prefetch (each covers the 1KB row).
            {
                const int prow2 = y + PFD2;
                if (prow2 < HH) l2_prefetch(src + prow2 * WW);
                const int prow1 = y + PFD1;
                if (prow1 < HH) l1_prefetch(src + prow1 * WW);
            }
            // Demand load row y+4 into slot (u+4)&7 (vacated row y-4).
            {
                const int row = y + 4;
                const int s = (u + 4) & 7;
                if (row < HH) {
                    const int4* rp = (const int4*)(src + row * WW);
                    int4 a = rp[0], b = rp[1];
                    ring[s][0] = a.x; ring[s][1] = a.y; ring[s][2] = a.z; ring[s][3] = a.w;
                    ring[s][4] = b.x; ring[s][5] = b.y; ring[s][6] = b.z; ring[s][7] = b.w;
                } else {
                    #pragma unroll
                    for (int t = 0; t < 8; ++t) ring[s][t] = NEG_I;
                }
            }

            int v[8];
            float acc[8];

            // ---- k = 3 ----
            #pragma unroll
            for (int j = 0; j < 8; ++j)
                v[j] = __vimax3_s32(ring[(u + 7) & 7][j], ring[u][j],
                                    ring[(u + 1) & 7][j]);
            {
                int L = __shfl_up_sync  (FULL, v[7], 1); if (l0)  L = NEG_I;
                int R = __shfl_down_sync(FULL, v[0], 1); if (l31) R = NEG_I;
                int m0 = __vimax3_s32(L, v[0], v[1]);
                int m7 = __vimax3_s32(v[6], v[7], R);
                acc[0] = w3 * __log2f(__int_as_float(m0));
                #pragma unroll
                for (int j = 1; j < 7; ++j)
                    acc[j] = w3 * __log2f(__int_as_float(
                                 __vimax3_s32(v[j - 1], v[j], v[j + 1])));
                acc[7] = w3 * __log2f(__int_as_float(m7));
            }

            // ---- k = 5 ----
            #pragma unroll
            for (int j = 0; j < 8; ++j)
                v[j] = __vimax3_s32(v[j], ring[(u + 6) & 7][j],
                                    ring[(u + 2) & 7][j]);
            {
                int p01 = imax2(v[0], v[1]), p23 = imax2(v[2], v[3]);
                int p45 = imax2(v[4], v[5]), p67 = imax2(v[6], v[7]);
                int Lp = __shfl_up_sync  (FULL, p67, 1);
                int L7 = __shfl_up_sync  (FULL, v[7], 1);
                int R0 = __shfl_down_sync(FULL, v[0], 1);
                int Rp = __shfl_down_sync(FULL, p01, 1);
                if (l0)  { Lp = NEG_I; L7 = NEG_I; }
                if (l31) { R0 = NEG_I; Rp = NEG_I; }
                int m[8];
                m[0] = __vimax3_s32(Lp,  p01, v[2]);
                m[1] = __vimax3_s32(L7,  p01, p23);
                m[2] = __vimax3_s32(p01, p23, v[4]);
                m[3] = __vimax3_s32(v[1], p23, p45);
                m[4] = __vimax3_s32(p23, p45, v[6]);
                m[5] = __vimax3_s32(v[3], p45, p67);
                m[6] = __vimax3_s32(p45, p67, R0);
                m[7] = __vimax3_s32(v[5], p67, Rp);
                #pragma unroll
                for (int j = 0; j < 8; ++j)
                    acc[j] = fmaf(w5, __log2f(__int_as_float(m[j])), acc[j]);
            }

            // ---- k = 7 ----
            #pragma unroll
            for (int j = 0; j < 8; ++j)
                v[j] = __vimax3_s32(v[j], ring[(u + 5) & 7][j],
                                    ring[(u + 3) & 7][j]);
            {
                int p01 = imax2(v[0], v[1]), p23 = imax2(v[2], v[3]);
                int p45 = imax2(v[4], v[5]), p67 = imax2(v[6], v[7]);
                int a03 = imax2(p01, p23),   a47 = imax2(p45, p67);
                int suf3 = imax2(v[5], p67); // cols 5..7
                int pre3 = imax2(p01, v[2]); // cols 0..2
                int Ls  = __shfl_up_sync  (FULL, suf3, 1);
                int Lq  = __shfl_up_sync  (FULL, p67, 1);
                int L7v = __shfl_up_sync  (FULL, v[7], 1);
                int R0v = __shfl_down_sync(FULL, v[0], 1);
                int Rq  = __shfl_down_sync(FULL, p01, 1);
                int Rp3 = __shfl_down_sync(FULL, pre3, 1);
                if (l0)  { Ls = NEG_I; Lq = NEG_I; L7v = NEG_I; }
                if (l31) { R0v = NEG_I; Rq = NEG_I; Rp3 = NEG_I; }
                int m[8];
                m[0] = imax2(Ls, a03);               // -3..3
                m[1] = __vimax3_s32(Lq,  a03, v[4]); // -2..4
                m[2] = __vimax3_s32(L7v, a03, p45);  // -1..5
                m[3] = __vimax3_s32(a03, p45, v[6]); //  0..6
                m[4] = __vimax3_s32(v[1], p23, a47); //  1..7
                m[5] = __vimax3_s32(p23, a47, R0v);  //  2..8
                m[6] = __vimax3_s32(v[3], a47, Rq);  //  3..9
                m[7] = imax2(a47, Rp3);              //  4..10
                #pragma unroll
                for (int j = 0; j < 8; ++j)
                    acc[j] = fmaf(w7, __log2f(__int_as_float(m[j])), acc[j]);
            }

            float* dp = dst + y * WW;
            ((float4*)dp)[0] = make_float4(acc[0], acc[1], acc[2], acc[3]);
            ((float4*)dp)[1] = make_float4(acc[4], acc[5], acc[6], acc[7]);
        }
    }
}

extern "C" void kernel_launch(void* const* d_in, const int* in_sizes, int n_in,
                              void* d_out, int out_size)
{
    const int* x = (const int*)d_in[0];
    float* out = (float*)d_out;

    const int planes = in_sizes[0] / (HH * WW);     // 512

    // Closed-form OLS slope weights (double on host); fold in log10(2).
    double l3 = log10(3.0), l5 = log10(5.0), l7 = log10(7.0);
    double mean = (l3 + l5 + l7) / 3.0;
    double c3 = l3 - mean, c5 = l5 - mean, c7 = l7 - mean;
    double s = c3 * c3 + c5 * c5 + c7 * c7;
    double L10_2 = 0.30102999566398119521;
    float w3 = (float)((c3 / s) * L10_2);
    float w5 = (float)((c5 / s) * L10_2);
    float w7 = (float)((c7 / s) * L10_2);

    const int tasks = planes * (HH / RPB);          // 4096
    dim3 grid(tasks);                               // one warp per block
    dim3 block(THREADS);
    holder_kernel<<<grid, block>>>(x, out, w3, w5, w7);
}

// round 15
// speedup vs baseline: 1.0909x; 1.0237x over previous
#include <cuda_runtime.h>
#include <math.h>

// LocalHolder2D: out = sum_i w_i * log10(maxpool_k(x)), k = 3,5,7
// x: (B=8, C=64, H=256, W=256) fp32, strictly positive.
// Centered OLS weights (sum w_i = 0) -> log10(1/(H*W)) offset cancels.
//
// R15 = R12 (one-warp blocks, register ring, VIMNMX3 int max tree, L2
// prefetch y+12, launch_bounds (32,16)) with ONE structural change: the
// demand load moves to AFTER the vertical-max reads and targets row y+5
// into slot (u+5)&7 (just vacated by rm3). All 8 ring slots now carry live
// rows and every load has 2 iterations (~470 cyc) of slack before first
// use (row y+5 is rp3 of output y+2), fully covering the ~250-cyc L2 hit
// that the y+12 prefetch stages. Same instruction count, same registers
// (full unroll -> pure SSA renaming). No L1 prefetch stage (R14: harmful).

#define HH 256
#define WW 256
#define RPB 32                 /* rows per warp-task */
#define THREADS 32
#define NEG_I ((int)0xff800000)   /* -inf bits */
#define PFD 12                 /* L2 prefetch distance in rows */

static __device__ __forceinline__ int imax2(int a, int b) { return a > b ? a : b; }

static __device__ __forceinline__ void l2_prefetch(const int* p) {
    asm volatile("prefetch.global.L2 [%0];" :: "l"(p));
}

__global__ __launch_bounds__(THREADS, 16)
void holder_kernel(const int* __restrict__ x, float* __restrict__ out,
                   float w3, float w5, float w7)
{
    const int lane = threadIdx.x & 31;
    const int task = blockIdx.x;                    // 4096 tasks
    const int plane = task >> 3;
    const int y0 = (task & 7) * RPB;                // multiple of 8

    const int* __restrict__ src = x   + (size_t)plane * (HH * WW) + lane * 8;
    float*     __restrict__ dst = out + (size_t)plane * (HH * WW) + lane * 8;

    const unsigned FULL = 0xffffffffu;
    const bool l0 = (lane == 0), l31 = (lane == 31);

    // ring[slot][col]; slot for row r is r & 7 (y0 % 8 == 0).
    int ring[8][8];

    // Prologue prefetch: rows y0+5 .. y0+PFD-1 into L2.
    #pragma unroll
    for (int j = 5; j < PFD; ++j) {
        const int row = y0 + j;
        if (row < HH) l2_prefetch(src + row * WW);
    }

    // Prologue: rows y0-3 .. y0+4 fill ALL 8 slots ((row&7) = (j+5)&7).
    #pragma unroll
    for (int j = 0; j < 8; ++j) {
        const int row = y0 - 3 + j;
        const int s = (j + 5) & 7;
        if (row >= 0) {
            const int4* rp = (const int4*)(src + row * WW);
            int4 a = rp[0], b = rp[1];
            ring[s][0] = a.x; ring[s][1] = a.y; ring[s][2] = a.z; ring[s][3] = a.w;
            ring[s][4] = b.x; ring[s][5] = b.y; ring[s][6] = b.z; ring[s][7] = b.w;
        } else {
            #pragma unroll
            for (int t = 0; t < 8; ++t) ring[s][t] = NEG_I;
        }
    }

    for (int ib = 0; ib < RPB; ib += 8) {
        #pragma unroll
        for (int u = 0; u < 8; ++u) {
            const int y = y0 + ib + u;            // output row; y & 7 == u
            // L2 prefetch far ahead (one inst covers the whole 1KB row).
            {
                const int prow = y + PFD;
                if (prow < HH) l2_prefetch(src + prow * WW);
            }

            int v[8];
            float acc[8];

            // ---- vertical k = 3 (rows y-1, y, y+1) ----
            #pragma unroll
            for (int j = 0; j < 8; ++j)
                v[j] = __vimax3_s32(ring[(u + 7) & 7][j], ring[u][j],
                                    ring[(u + 1) & 7][j]);

            // ---- vertical k = 5 (add rows y-2, y+2) ----
            int v5[8];
            #pragma unroll
            for (int j = 0; j < 8; ++j)
                v5[j] = __vimax3_s32(v[j], ring[(u + 6) & 7][j],
                                     ring[(u + 2) & 7][j]);

            // ---- vertical k = 7 (add rows y-3, y+3); consumes rm3 ----
            int v7[8];
            #pragma unroll
            for (int j = 0; j < 8; ++j)
                v7[j] = __vimax3_s32(v5[j], ring[(u + 5) & 7][j],
                                     ring[(u + 3) & 7][j]);

            // Load row y+5 into slot (u+5)&7 (rm3 just consumed above).
            // First use: rp3 of output y+2 -> 2 iterations of slack.
            {
                const int row = y + 5;
                const int s = (u + 5) & 7;
                if (row < HH) {
                    const int4* rp = (const int4*)(src + row * WW);
                    int4 a = rp[0], b = rp[1];
                    ring[s][0] = a.x; ring[s][1] = a.y; ring[s][2] = a.z; ring[s][3] = a.w;
                    ring[s][4] = b.x; ring[s][5] = b.y; ring[s][6] = b.z; ring[s][7] = b.w;
                } else {
                    #pragma unroll
                    for (int t = 0; t < 8; ++t) ring[s][t] = NEG_I;
                }
            }

            // ---- horizontal k = 3 ----
            {
                int L = __shfl_up_sync  (FULL, v[7], 1); if (l0)  L = NEG_I;
                int R = __shfl_down_sync(FULL, v[0], 1); if (l31) R = NEG_I;
                int m0 = __vimax3_s32(L, v[0], v[1]);
                int m7 = __vimax3_s32(v[6], v[7], R);
                acc[0] = w3 * __log2f(__int_as_float(m0));
                #pragma unroll
                for (int j = 1; j < 7; ++j)
                    acc[j] = w3 * __log2f(__int_as_float(
                                 __vimax3_s32(v[j - 1], v[j], v[j + 1])));
                acc[7] = w3 * __log2f(__int_as_float(m7));
            }

            // ---- horizontal k = 5 ----
            {
                int p01 = imax2(v5[0], v5[1]), p23 = imax2(v5[2], v5[3]);
                int p45 = imax2(v5[4], v5[5]), p67 = imax2(v5[6], v5[7]);
                int Lp = __shfl_up_sync  (FULL, p67, 1);
                int L7 = __shfl_up_sync  (FULL, v5[7], 1);
                int R0 = __shfl_down_sync(FULL, v5[0], 1);
                int Rp = __shfl_down_sync(FULL, p01, 1);
                if (l0)  { Lp = NEG_I; L7 = NEG_I; }
                if (l31) { R0 = NEG_I; Rp = NEG_I; }
                int m[8];
                m[0] = __vimax3_s32(Lp,   p01, v5[2]);
                m[1] = __vimax3_s32(L7,   p01, p23);
                m[2] = __vimax3_s32(p01,  p23, v5[4]);
                m[3] = __vimax3_s32(v5[1], p23, p45);
                m[4] = __vimax3_s32(p23,  p45, v5[6]);
                m[5] = __vimax3_s32(v5[3], p45, p67);
                m[6] = __vimax3_s32(p45,  p67, R0);
                m[7] = __vimax3_s32(v5[5], p67, Rp);
                #pragma unroll
                for (int j = 0; j < 8; ++j)
                    acc[j] = fmaf(w5, __log2f(__int_as_float(m[j])), acc[j]);
            }

            // ---- horizontal k = 7 ----
            {
                int p01 = imax2(v7[0], v7[1]), p23 = imax2(v7[2], v7[3]);
                int p45 = imax2(v7[4], v7[5]), p67 = imax2(v7[6], v7[7]);
                int a03 = imax2(p01, p23),     a47 = imax2(p45, p67);
                int suf3 = imax2(v7[5], p67); // cols 5..7
                int pre3 = imax2(p01, v7[2]); // cols 0..2
                int Ls  = __shfl_up_sync  (FULL, suf3, 1);
                int Lq  = __shfl_up_sync  (FULL, p67, 1);
                int L7v = __shfl_up_sync  (FULL, v7[7], 1);
                int R0v = __shfl_down_sync(FULL, v7[0], 1);
                int Rq  = __shfl_down_sync(FULL, p01, 1);
                int Rp3 = __shfl_down_sync(FULL, pre3, 1);
                if (l0)  { Ls = NEG_I; Lq = NEG_I; L7v = NEG_I; }
                if (l31) { R0v = NEG_I; Rq = NEG_I; Rp3 = NEG_I; }
                int m[8];
                m[0] = imax2(Ls, a03);                 // -3..3
                m[1] = __vimax3_s32(Lq,   a03, v7[4]); // -2..4
                m[2] = __vimax3_s32(L7v,  a03, p45);   // -1..5
                m[3] = __vimax3_s32(a03,  p45, v7[6]); //  0..6
                m[4] = __vimax3_s32(v7[1], p23, a47);  //  1..7
                m[5] = __vimax3_s32(p23,  a47, R0v);   //  2..8
                m[6] = __vimax3_s32(v7[3], a47, Rq);   //  3..9
                m[7] = imax2(a47, Rp3);                //  4..10
                #pragma unroll
                for (int j = 0; j < 8; ++j)
                    acc[j] = fmaf(w7, __log2f(__int_as_float(m[j])), acc[j]);
            }

            float* dp = dst + y * WW;
            ((float4*)dp)[0] = make_float4(acc[0], acc[1], acc[2], acc[3]);
            ((float4*)dp)[1] = make_float4(acc[4], acc[5], acc[6], acc[7]);
        }
    }
}

extern "C" void kernel_launch(void* const* d_in, const int* in_sizes, int n_in,
                              void* d_out, int out_size)
{
    const int* x = (const int*)d_in[0];
    float* out = (float*)d_out;

    const int planes = in_sizes[0] / (HH * WW);     // 512

    // Closed-form OLS slope weights (double on host); fold in log10(2).
    double l3 = log10(3.0), l5 = log10(5.0), l7 = log10(7.0);
    double mean = (l3 + l5 + l7) / 3.0;
    double c3 = l3 - mean, c5 = l5 - mean, c7 = l7 - mean;
    double s = c3 * c3 + c5 * c5 + c7 * c7;
    double L10_2 = 0.30102999566398119521;
    float w3 = (float)((c3 / s) * L10_2);
    float w5 = (float)((c5 / s) * L10_2);
    float w7 = (float)((c7 / s) * L10_2);

    const int tasks = planes * (HH / RPB);          // 4096
    dim3 grid(tasks);                               // one warp per block
    dim3 block(THREADS);
    holder_kernel<<<grid, block>>>(x, out, w3, w5, w7);
}